// round 9
// baseline (speedup 1.0000x reference)
#include <cuda_runtime.h>
#include <cuda_bf16.h>
#include <cstdint>

#define FDIM 128
#define MAXN 50001
#define NPAD 50176      // 392 * 128, padded node count
#define MAXE 1000000
#define AP2 68          // smem pitch in uint2 (64 k-pairs + 4 pad), conflict-free

// ---------------------------------------------------------------------------
// Device scratch (allocation-free per harness rules)
__device__ unsigned int g_ctrl[1];               // [0]=dtype flag (0 => int64)
__device__ int g_row_ptr[MAXN];
// W^T interleaved hi/lo pairs, pitch AP2: g_wt[n*AP2 + k/2] = {hi2, lo2}
__device__ uint2 g_wt[FDIM * AP2];

// ---------------------------------------------------------------------------
// 1) dtype detect over a 32K-pair window: if int64, odd words are hi(u[i])=0;
//    if int32, odd words are sorted-u values beyond index 0 — nonzero.
__global__ void detect_k(const unsigned int* __restrict__ w, int npairs) {
    unsigned int local = 0;
    for (int i = blockIdx.x * blockDim.x + threadIdx.x; i < npairs;
         i += gridDim.x * blockDim.x)
        local |= w[2 * i + 1];
    if (local) atomicOr(&g_ctrl[0], 1u);
}

// 2) rowptr + W prep: CSR row_ptr by binary search (u sorted), W^T hi/lo.
__global__ void rowptr_k(const void* __restrict__ edges,
                         const float* __restrict__ W, int E, int nN) {
    const bool is64 = (g_ctrl[0] == 0);
    const long long* e64 = (const long long*)edges;
    const int* e32 = (const int*)edges;
    const int i = blockIdx.x * blockDim.x + threadIdx.x;
    if (i <= nN) {
        if (i == nN) g_row_ptr[nN] = E;
        else {
            int lo = 0, hi = E;
            while (lo < hi) {
                int mid = (lo + hi) >> 1;
                long long um = is64 ? e64[mid] : (long long)e32[mid];
                if (um < (long long)i) lo = mid + 1; else hi = mid;
            }
            g_row_ptr[i] = lo;
        }
    }
    if (i < FDIM * (FDIM / 2)) {
        const int n = i >> 6, kp = i & 63;
        const int k = kp * 2;
        const float w0 = W[k * FDIM + n];
        const float w1 = W[(k + 1) * FDIM + n];
        const __nv_bfloat16 h0 = __float2bfloat16(w0);
        const __nv_bfloat16 h1 = __float2bfloat16(w1);
        uint2 o;
        asm("cvt.rn.bf16x2.f32 %0, %1, %2;" : "=r"(o.x)
            : "f"(__bfloat162float(h1)), "f"(__bfloat162float(h0)));
        asm("cvt.rn.bf16x2.f32 %0, %1, %2;" : "=r"(o.y)
            : "f"(w1 - __bfloat162float(h1)), "f"(w0 - __bfloat162float(h0)));
        g_wt[n * AP2 + kp] = o;
    }
}

// ---------------------------------------------------------------------------
__device__ __forceinline__ uint32_t pack_hi2(float a, float b) {
    uint32_t r;
    asm("cvt.rn.bf16x2.f32 %0, %1, %2;" : "=r"(r) : "f"(b), "f"(a));
    return r;
}
__device__ __forceinline__ float bf16_of(float a) {
    __nv_bfloat16 h = __float2bfloat16(a);
    return __bfloat162float(h);
}
__device__ __forceinline__ void mma_bf16(float* c, const uint32_t* a, const uint32_t* b) {
    asm volatile(
        "mma.sync.aligned.m16n8k16.row.col.f32.bf16.bf16.f32 "
        "{%0,%1,%2,%3}, {%4,%5,%6,%7}, {%8,%9}, {%0,%1,%2,%3};"
        : "+f"(c[0]), "+f"(c[1]), "+f"(c[2]), "+f"(c[3])
        : "r"(a[0]), "r"(a[1]), "r"(a[2]), "r"(a[3]), "r"(b[0]), "r"(b[1]));
}

// ---------------------------------------------------------------------------
// 3) FUSED kernel: block b owns nodes [b*128, b*128+128).
//    Phase 0: stage B (full 128x128 hi/lo W^T, 69.6KB) into smem.
//    Phase 1: warp w gathers its 16 nodes (rows w*16..w*16+15) from x via CSR,
//             fp32 accum, writes bf16 hi/lo interleaved pairs into smem A tile.
//    Phase 2: 8 warps x (16M x 128N) mma.sync bf16, 3-pass hi/lo split, from
//             smem only. A never touches global memory.
#define SM_A 0
#define SM_B (128 * AP2)
#define SM_BYTES (2 * 128 * AP2 * 8)

template <bool IS64>
__device__ __forceinline__ void fused_body(const float* __restrict__ x,
                                           const void* __restrict__ edges,
                                           const float* __restrict__ bias,
                                           float* __restrict__ out,
                                           int E, int nN) {
    extern __shared__ __align__(16) uint2 sm[];
    const int tid = threadIdx.x;
    const int wid = tid >> 5, lane = tid & 31;
    const int mbase = blockIdx.x * 128;

    // ---- Phase 0: stage B tile (disjoint smem from A; sync below covers) ----
    {
        const uint4* __restrict__ src = (const uint4*)g_wt;
        uint4* __restrict__ dst = (uint4*)(sm + SM_B);
#pragma unroll
        for (int i = 0; i < 17; i++)
            dst[i * 256 + tid] = src[i * 256 + tid];
    }

    // ---- Phase 1: gather my 16 rows ----
    const float4* __restrict__ xr = (const float4*)x;
    const long long* __restrict__ v64 = (const long long*)edges + E;
    const int* __restrict__ v32 = (const int*)edges + E;
#pragma unroll 1
    for (int i = 0; i < 16; i++) {
        const int row = wid * 16 + i;
        const int node = mbase + row;
        float4 accA = make_float4(0.f, 0.f, 0.f, 0.f);
        float4 accB = make_float4(0.f, 0.f, 0.f, 0.f);
        if (node < nN) {
            const int s = g_row_ptr[node];
            const int e = g_row_ptr[node + 1];
            int j = s;
            for (; j + 4 <= e; j += 4) {
                const int a0 = IS64 ? (int)v64[j + 0] : v32[j + 0];
                const int a1 = IS64 ? (int)v64[j + 1] : v32[j + 1];
                const int a2 = IS64 ? (int)v64[j + 2] : v32[j + 2];
                const int a3 = IS64 ? (int)v64[j + 3] : v32[j + 3];
                const float4 x0 = __ldg(&xr[(size_t)a0 * 32 + lane]);
                const float4 x1 = __ldg(&xr[(size_t)a1 * 32 + lane]);
                const float4 x2 = __ldg(&xr[(size_t)a2 * 32 + lane]);
                const float4 x3 = __ldg(&xr[(size_t)a3 * 32 + lane]);
                accA.x += x0.x; accA.y += x0.y; accA.z += x0.z; accA.w += x0.w;
                accB.x += x1.x; accB.y += x1.y; accB.z += x1.z; accB.w += x1.w;
                accA.x += x2.x; accA.y += x2.y; accA.z += x2.z; accA.w += x2.w;
                accB.x += x3.x; accB.y += x3.y; accB.z += x3.z; accB.w += x3.w;
            }
            for (; j < e; j++) {
                const int v = IS64 ? (int)v64[j] : v32[j];
                const float4 xv = __ldg(&xr[(size_t)v * 32 + lane]);
                accA.x += xv.x; accA.y += xv.y; accA.z += xv.z; accA.w += xv.w;
            }
            accA.x += accB.x; accA.y += accB.y; accA.z += accB.z; accA.w += accB.w;
        }
        uint4 o;   // {hi(4l),hi(4l+1)} {lo pair} {hi(4l+2),hi(4l+3)} {lo pair}
        o.x = pack_hi2(accA.x, accA.y);
        o.y = pack_hi2(accA.x - bf16_of(accA.x), accA.y - bf16_of(accA.y));
        o.z = pack_hi2(accA.z, accA.w);
        o.w = pack_hi2(accA.z - bf16_of(accA.z), accA.w - bf16_of(accA.w));
        *(uint4*)&sm[SM_A + row * AP2 + 2 * lane] = o;
    }
    __syncthreads();

    // ---- Phase 2: GEMM from smem ----
    const int qr = lane >> 2;
    const int qc = (lane & 3) * 2;

    float acc[16][4];
#pragma unroll
    for (int nt = 0; nt < 16; nt++)
#pragma unroll
        for (int q = 0; q < 4; q++) acc[nt][q] = 0.f;

    const int ar = wid * 16 + qr;
#pragma unroll
    for (int ks = 0; ks < 8; ks++) {
        const int kp0 = ks * 8 + (lane & 3);
        const uint2 a0 = sm[SM_A + ar * AP2 + kp0];
        const uint2 a1 = sm[SM_A + (ar + 8) * AP2 + kp0];
        const uint2 a2 = sm[SM_A + ar * AP2 + kp0 + 4];
        const uint2 a3 = sm[SM_A + (ar + 8) * AP2 + kp0 + 4];
        const uint32_t ahi[4] = {a0.x, a1.x, a2.x, a3.x};
        const uint32_t alo[4] = {a0.y, a1.y, a2.y, a3.y};
#pragma unroll
        for (int nt = 0; nt < 16; nt++) {
            const int brow = nt * 8 + qr;
            const uint2 b0 = sm[SM_B + brow * AP2 + kp0];
            const uint2 b1 = sm[SM_B + brow * AP2 + kp0 + 4];
            const uint32_t bhi[2] = {b0.x, b1.x};
            const uint32_t blo[2] = {b0.y, b1.y};
            mma_bf16(acc[nt], ahi, bhi);
            mma_bf16(acc[nt], ahi, blo);
            mma_bf16(acc[nt], alo, bhi);
        }
    }

    // ---- Epilogue ----
    const int m0 = mbase + wid * 16 + qr;
#pragma unroll
    for (int nt = 0; nt < 16; nt++) {
        const int n0 = nt * 8 + qc;
        const float2 bv = *(const float2*)&bias[n0];
        if (m0 < nN) {
            float2 r = make_float2(acc[nt][0] + bv.x, acc[nt][1] + bv.y);
            *(float2*)&out[(size_t)m0 * FDIM + n0] = r;
        }
        if (m0 + 8 < nN) {
            float2 r = make_float2(acc[nt][2] + bv.x, acc[nt][3] + bv.y);
            *(float2*)&out[(size_t)(m0 + 8) * FDIM + n0] = r;
        }
    }
}

__global__ void __launch_bounds__(256) fused_k(const float* __restrict__ x,
                                               const void* __restrict__ edges,
                                               const float* __restrict__ bias,
                                               float* __restrict__ out,
                                               int E, int nN) {
    if (g_ctrl[0] == 0) fused_body<true>(x, edges, bias, out, E, nN);
    else fused_body<false>(x, edges, bias, out, E, nN);
}

// ---------------------------------------------------------------------------
extern "C" void kernel_launch(void* const* d_in, const int* in_sizes, int n_in,
                              void* d_out, int out_size) {
    const float* x = (const float*)d_in[0];
    const void* edges = d_in[1];
    const float* W = (const float*)d_in[2];
    const float* bias = (const float*)d_in[3];
    float* out = (float*)d_out;

    const int nN = in_sizes[0] / FDIM;
    int E = in_sizes[1] / 2;
    if (E > MAXE) E = MAXE;

    void* ctrl = nullptr;
    cudaGetSymbolAddress(&ctrl, g_ctrl);
    cudaMemsetAsync(ctrl, 0, sizeof(unsigned int));

    cudaFuncSetAttribute(fused_k, cudaFuncAttributeMaxDynamicSharedMemorySize, SM_BYTES);

    int npairs = E < 32768 ? E : 32768;
    detect_k<<<16, 256>>>((const unsigned int*)edges, npairs);
    rowptr_k<<<(nN + 256) / 256, 256>>>(edges, W, E, nN);
    fused_k<<<NPAD / 128, 256, SM_BYTES>>>(x, edges, bias, out, E, nN);
}

// round 10
// speedup vs baseline: 1.6920x; 1.6920x over previous
#include <cuda_runtime.h>
#include <cuda_bf16.h>
#include <cstdint>

#define FDIM 128
#define MAXN 50001
#define NPAD 50176      // 392 * 128, padded node count
#define MAXE 1000000
#define AP2 68          // pitch in uint2 (64 k-pairs + 4 pad) -> conflict-free LDS.64

// ---------------------------------------------------------------------------
// Device scratch (allocation-free per harness rules)
__device__ unsigned int g_ctrl[1];               // [0]=dtype flag (0 => int64)
__device__ int g_row_ptr[MAXN];
// Aggregate, interleaved hi/lo pairs: row r, even k: {hi(k),hi(k+1),lo(k),lo(k+1)}
__device__ __nv_bfloat16 g_a[(size_t)NPAD * 256];
// W^T interleaved hi/lo pairs, pitch AP2: g_wt[n*AP2 + k/2] = {hi2, lo2}
__device__ uint2 g_wt[FDIM * AP2];

// ---------------------------------------------------------------------------
// 1) dtype detect, 512 pairs: if int64, odd words are hi(u[i])=0; if int32,
//    odd words are sorted-unique u values beyond index 0 — some are nonzero.
__global__ void detect_k(const unsigned int* __restrict__ w, int npairs) {
    unsigned int local = 0;
    for (int i = threadIdx.x; i < npairs; i += blockDim.x)
        local |= w[2 * i + 1];
    if (local) atomicOr(&g_ctrl[0], 1u);
}

// 2) rowptr + W prep: CSR row_ptr by binary search (u sorted), W^T hi/lo.
__global__ void rowptr_k(const void* __restrict__ edges,
                         const float* __restrict__ W, int E, int nN) {
    const bool is64 = (g_ctrl[0] == 0);
    const long long* e64 = (const long long*)edges;
    const int* e32 = (const int*)edges;
    const int i = blockIdx.x * blockDim.x + threadIdx.x;
    if (i <= nN) {
        if (i == nN) g_row_ptr[nN] = E;
        else {
            int lo = 0, hi = E;
            while (lo < hi) {
                int mid = (lo + hi) >> 1;
                long long um = is64 ? e64[mid] : (long long)e32[mid];
                if (um < (long long)i) lo = mid + 1; else hi = mid;
            }
            g_row_ptr[i] = lo;
        }
    }
    if (i < FDIM * (FDIM / 2)) {
        const int n = i >> 6, kp = i & 63;
        const int k = kp * 2;
        const float w0 = W[k * FDIM + n];
        const float w1 = W[(k + 1) * FDIM + n];
        const __nv_bfloat16 h0 = __float2bfloat16(w0);
        const __nv_bfloat16 h1 = __float2bfloat16(w1);
        uint2 o;
        asm("cvt.rn.bf16x2.f32 %0, %1, %2;" : "=r"(o.x)
            : "f"(__bfloat162float(h1)), "f"(__bfloat162float(h0)));
        asm("cvt.rn.bf16x2.f32 %0, %1, %2;" : "=r"(o.y)
            : "f"(w1 - __bfloat162float(h1)), "f"(w0 - __bfloat162float(h0)));
        g_wt[n * AP2 + kp] = o;
    }
}

// ---------------------------------------------------------------------------
// 3) aggregate: static warp-per-node, v read inline from edge_index,
//    fp32 accum, interleaved bf16 hi/lo out. (R8 version — at LTS floor.)
__device__ __forceinline__ uint32_t pack_hi2(float a, float b) {
    uint32_t r;
    asm("cvt.rn.bf16x2.f32 %0, %1, %2;" : "=r"(r) : "f"(b), "f"(a));
    return r;
}
__device__ __forceinline__ float bf16_of(float a) {
    __nv_bfloat16 h = __float2bfloat16(a);
    return __bfloat162float(h);
}

template <bool IS64>
__device__ __forceinline__ void agg_body(const float* __restrict__ x,
                                         const void* __restrict__ edges,
                                         int E, int nN) {
    const int lane = threadIdx.x & 31;
    const int gw = (blockIdx.x * blockDim.x + threadIdx.x) >> 5;
    const int nw = (gridDim.x * blockDim.x) >> 5;
    const float4* __restrict__ xr = (const float4*)x;
    uint4* __restrict__ ga4 = (uint4*)g_a;
    const long long* __restrict__ v64 = (const long long*)edges + E;
    const int* __restrict__ v32 = (const int*)edges + E;

    for (int node = gw; node < NPAD; node += nw) {
        float4 accA = make_float4(0.f, 0.f, 0.f, 0.f);
        float4 accB = make_float4(0.f, 0.f, 0.f, 0.f);
        if (node < nN) {
            const int s = g_row_ptr[node];
            const int e = g_row_ptr[node + 1];
            int j = s;
            for (; j + 4 <= e; j += 4) {
                const int v0 = IS64 ? (int)v64[j + 0] : v32[j + 0];
                const int v1 = IS64 ? (int)v64[j + 1] : v32[j + 1];
                const int v2 = IS64 ? (int)v64[j + 2] : v32[j + 2];
                const int v3 = IS64 ? (int)v64[j + 3] : v32[j + 3];
                const float4 x0 = __ldg(&xr[(size_t)v0 * 32 + lane]);
                const float4 x1 = __ldg(&xr[(size_t)v1 * 32 + lane]);
                const float4 x2 = __ldg(&xr[(size_t)v2 * 32 + lane]);
                const float4 x3 = __ldg(&xr[(size_t)v3 * 32 + lane]);
                accA.x += x0.x; accA.y += x0.y; accA.z += x0.z; accA.w += x0.w;
                accB.x += x1.x; accB.y += x1.y; accB.z += x1.z; accB.w += x1.w;
                accA.x += x2.x; accA.y += x2.y; accA.z += x2.z; accA.w += x2.w;
                accB.x += x3.x; accB.y += x3.y; accB.z += x3.z; accB.w += x3.w;
            }
            for (; j < e; j++) {
                const int v = IS64 ? (int)v64[j] : v32[j];
                const float4 xv = __ldg(&xr[(size_t)v * 32 + lane]);
                accA.x += xv.x; accA.y += xv.y; accA.z += xv.z; accA.w += xv.w;
            }
            accA.x += accB.x; accA.y += accB.y; accA.z += accB.z; accA.w += accB.w;
        }
        uint4 o;
        o.x = pack_hi2(accA.x, accA.y);
        o.y = pack_hi2(accA.x - bf16_of(accA.x), accA.y - bf16_of(accA.y));
        o.z = pack_hi2(accA.z, accA.w);
        o.w = pack_hi2(accA.z - bf16_of(accA.z), accA.w - bf16_of(accA.w));
        ga4[(size_t)node * 32 + lane] = o;
    }
}

__global__ void __launch_bounds__(256) agg_k(const float* __restrict__ x,
                                             const void* __restrict__ edges,
                                             int E, int nN) {
    if (g_ctrl[0] == 0) agg_body<true>(x, edges, E, nN);
    else agg_body<false>(x, edges, E, nN);
}

// ---------------------------------------------------------------------------
// 4) GEMM: out = agg @ W + bias, mma.sync m16n8k16 bf16 3-pass hi/lo split.
//    Block 128 thr = 4 warps; block tile 64M x 128N; warp tile 32M x 64N
//    (2 m-frags x 8 n-frags). launch_bounds(128,3) -> 170-reg budget (~110
//    used, NO SPILLS), 12 warps/SM, smem B 69.6KB x 3 = 208KB.
__device__ __forceinline__ void mma_bf16(float* c, const uint32_t* a, const uint32_t* b) {
    asm volatile(
        "mma.sync.aligned.m16n8k16.row.col.f32.bf16.bf16.f32 "
        "{%0,%1,%2,%3}, {%4,%5,%6,%7}, {%8,%9}, {%0,%1,%2,%3};"
        : "+f"(c[0]), "+f"(c[1]), "+f"(c[2]), "+f"(c[3])
        : "r"(a[0]), "r"(a[1]), "r"(a[2]), "r"(a[3]), "r"(b[0]), "r"(b[1]));
}

#define SM_BYTES (128 * AP2 * 8)

__global__ void __launch_bounds__(128, 3) gemm_k(const float* __restrict__ bias,
                                                 float* __restrict__ out, int nN) {
    extern __shared__ __align__(16) uint2 smB[];   // [128][AP2] uint2
    const int tid = threadIdx.x;
    const int wid = tid >> 5, lane = tid & 31;
    const int mwarp = wid & 1, nwarp = wid >> 1;
    const int mbase = blockIdx.x * 64 + mwarp * 32;
    const int nbase = nwarp * 64;

    // Stage full B (128 rows x 34 uint4, pitch preserved) = 4352 uint4.
    {
        const uint4* __restrict__ src = (const uint4*)g_wt;
        uint4* __restrict__ dst = (uint4*)smB;
#pragma unroll
        for (int i = 0; i < 34; i++)
            dst[i * 128 + tid] = src[i * 128 + tid];
    }
    __syncthreads();

    const int qr = lane >> 2;          // fragment row within 8-row group
    const int qc = (lane & 3) * 2;     // fragment k/n offset

    float acc[2][8][4];
#pragma unroll
    for (int j = 0; j < 2; j++)
#pragma unroll
        for (int nt = 0; nt < 8; nt++)
#pragma unroll
            for (int q = 0; q < 4; q++) acc[j][nt][q] = 0.f;

    const uint2* __restrict__ ga = (const uint2*)g_a;   // 8B = {hi2, lo2}
    const int r0 = mbase + qr;          // m-frag 0 rows r0, r0+8
    const int r1 = r0 + 16;             // m-frag 1 rows r1, r1+8

    uint2 nx[8];
    {
        const int kp = qc >> 1;         // ks = 0
        nx[0] = __ldg(&ga[(size_t)r0 * 64 + kp]);
        nx[1] = __ldg(&ga[(size_t)(r0 + 8) * 64 + kp]);
        nx[2] = __ldg(&ga[(size_t)r0 * 64 + kp + 4]);
        nx[3] = __ldg(&ga[(size_t)(r0 + 8) * 64 + kp + 4]);
        nx[4] = __ldg(&ga[(size_t)r1 * 64 + kp]);
        nx[5] = __ldg(&ga[(size_t)(r1 + 8) * 64 + kp]);
        nx[6] = __ldg(&ga[(size_t)r1 * 64 + kp + 4]);
        nx[7] = __ldg(&ga[(size_t)(r1 + 8) * 64 + kp + 4]);
    }

#pragma unroll
    for (int ks = 0; ks < 8; ks++) {
        const uint32_t ahi0[4] = {nx[0].x, nx[1].x, nx[2].x, nx[3].x};
        const uint32_t alo0[4] = {nx[0].y, nx[1].y, nx[2].y, nx[3].y};
        const uint32_t ahi1[4] = {nx[4].x, nx[5].x, nx[6].x, nx[7].x};
        const uint32_t alo1[4] = {nx[4].y, nx[5].y, nx[6].y, nx[7].y};
        if (ks < 7) {
            const int kp = ((ks + 1) * 16 + qc) >> 1;
            nx[0] = __ldg(&ga[(size_t)r0 * 64 + kp]);
            nx[1] = __ldg(&ga[(size_t)(r0 + 8) * 64 + kp]);
            nx[2] = __ldg(&ga[(size_t)r0 * 64 + kp + 4]);
            nx[3] = __ldg(&ga[(size_t)(r0 + 8) * 64 + kp + 4]);
            nx[4] = __ldg(&ga[(size_t)r1 * 64 + kp]);
            nx[5] = __ldg(&ga[(size_t)(r1 + 8) * 64 + kp]);
            nx[6] = __ldg(&ga[(size_t)r1 * 64 + kp + 4]);
            nx[7] = __ldg(&ga[(size_t)(r1 + 8) * 64 + kp + 4]);
        }
        const int kp0 = (ks * 16 + qc) >> 1;
#pragma unroll
        for (int nt = 0; nt < 8; nt++) {
            const int brow = nbase + nt * 8 + qr;
            const uint2 b0 = smB[brow * AP2 + kp0];
            const uint2 b1 = smB[brow * AP2 + kp0 + 4];
            const uint32_t bhi[2] = {b0.x, b1.x};
            const uint32_t blo[2] = {b0.y, b1.y};
            mma_bf16(acc[0][nt], ahi0, bhi);
            mma_bf16(acc[0][nt], ahi0, blo);
            mma_bf16(acc[0][nt], alo0, bhi);
            mma_bf16(acc[1][nt], ahi1, bhi);
            mma_bf16(acc[1][nt], ahi1, blo);
            mma_bf16(acc[1][nt], alo1, bhi);
        }
    }

    // Epilogue: frag j rows m0 = mbase + j*16 + qr, m0+8; cols nbase+nt*8+qc
#pragma unroll
    for (int j = 0; j < 2; j++) {
        const int m0 = mbase + j * 16 + qr;
#pragma unroll
        for (int nt = 0; nt < 8; nt++) {
            const int n0 = nbase + nt * 8 + qc;
            const float2 bv = *(const float2*)&bias[n0];
            if (m0 < nN) {
                float2 r = make_float2(acc[j][nt][0] + bv.x, acc[j][nt][1] + bv.y);
                *(float2*)&out[(size_t)m0 * FDIM + n0] = r;
            }
            if (m0 + 8 < nN) {
                float2 r = make_float2(acc[j][nt][2] + bv.x, acc[j][nt][3] + bv.y);
                *(float2*)&out[(size_t)(m0 + 8) * FDIM + n0] = r;
            }
        }
    }
}

// ---------------------------------------------------------------------------
extern "C" void kernel_launch(void* const* d_in, const int* in_sizes, int n_in,
                              void* d_out, int out_size) {
    const float* x = (const float*)d_in[0];
    const void* edges = d_in[1];
    const float* W = (const float*)d_in[2];
    const float* bias = (const float*)d_in[3];
    float* out = (float*)d_out;

    const int nN = in_sizes[0] / FDIM;
    int E = in_sizes[1] / 2;
    if (E > MAXE) E = MAXE;

    void* ctrl = nullptr;
    cudaGetSymbolAddress(&ctrl, g_ctrl);
    cudaMemsetAsync(ctrl, 0, sizeof(unsigned int));

    cudaFuncSetAttribute(gemm_k, cudaFuncAttributeMaxDynamicSharedMemorySize, SM_BYTES);

    int npairs = E < 512 ? E : 512;
    detect_k<<<1, 256>>>((const unsigned int*)edges, npairs);
    rowptr_k<<<(nN + 256) / 256, 256>>>(edges, W, E, nN);
    agg_k<<<1184, 256>>>(x, edges, E, nN);
    gemm_k<<<NPAD / 64, 128, SM_BYTES>>>(bias, out, nN);
}

// round 11
// speedup vs baseline: 1.7227x; 1.0182x over previous
#include <cuda_runtime.h>
#include <cuda_bf16.h>
#include <cstdint>

#define FDIM 128
#define MAXN 50001
#define NPAD 50176      // 392 * 128, padded node count
#define MAXE 1000000
#define AP2 68          // pitch in uint2 (64 k-pairs + 4 pad) -> conflict-free LDS.64
#define NTILES (NPAD / 64)   // 784 m-tiles of 64 rows

// ---------------------------------------------------------------------------
// Device scratch (allocation-free per harness rules)
__device__ unsigned int g_ctrl[1];               // [0]=dtype flag (0 => int64)
__device__ int g_row_ptr[MAXN];
// Aggregate, interleaved hi/lo pairs: row r, even k: {hi(k),hi(k+1),lo(k),lo(k+1)}
__device__ __nv_bfloat16 g_a[(size_t)NPAD * 256];
// W^T interleaved hi/lo pairs, pitch AP2: g_wt[n*AP2 + k/2] = {hi2, lo2}
__device__ uint2 g_wt[FDIM * AP2];

// ---------------------------------------------------------------------------
// 1) dtype detect, 512 pairs: if int64, odd words are hi(u[i])=0; if int32,
//    odd words are sorted-unique u values beyond index 0 — some are nonzero.
__global__ void detect_k(const unsigned int* __restrict__ w, int npairs) {
    unsigned int local = 0;
    for (int i = threadIdx.x; i < npairs; i += blockDim.x)
        local |= w[2 * i + 1];
    if (local) atomicOr(&g_ctrl[0], 1u);
}

// 2) rowptr + W prep: CSR row_ptr by binary search (u sorted), W^T hi/lo.
__global__ void rowptr_k(const void* __restrict__ edges,
                         const float* __restrict__ W, int E, int nN) {
    const bool is64 = (g_ctrl[0] == 0);
    const long long* e64 = (const long long*)edges;
    const int* e32 = (const int*)edges;
    const int i = blockIdx.x * blockDim.x + threadIdx.x;
    if (i <= nN) {
        if (i == nN) g_row_ptr[nN] = E;
        else {
            int lo = 0, hi = E;
            while (lo < hi) {
                int mid = (lo + hi) >> 1;
                long long um = is64 ? e64[mid] : (long long)e32[mid];
                if (um < (long long)i) lo = mid + 1; else hi = mid;
            }
            g_row_ptr[i] = lo;
        }
    }
    if (i < FDIM * (FDIM / 2)) {
        const int n = i >> 6, kp = i & 63;
        const int k = kp * 2;
        const float w0 = W[k * FDIM + n];
        const float w1 = W[(k + 1) * FDIM + n];
        const __nv_bfloat16 h0 = __float2bfloat16(w0);
        const __nv_bfloat16 h1 = __float2bfloat16(w1);
        uint2 o;
        asm("cvt.rn.bf16x2.f32 %0, %1, %2;" : "=r"(o.x)
            : "f"(__bfloat162float(h1)), "f"(__bfloat162float(h0)));
        asm("cvt.rn.bf16x2.f32 %0, %1, %2;" : "=r"(o.y)
            : "f"(w1 - __bfloat162float(h1)), "f"(w0 - __bfloat162float(h0)));
        g_wt[n * AP2 + kp] = o;
    }
}

// ---------------------------------------------------------------------------
// 3) aggregate: static warp-per-node, v read inline from edge_index,
//    fp32 accum, interleaved bf16 hi/lo out. (Unchanged — at L2 floor.)
__device__ __forceinline__ uint32_t pack_hi2(float a, float b) {
    uint32_t r;
    asm("cvt.rn.bf16x2.f32 %0, %1, %2;" : "=r"(r) : "f"(b), "f"(a));
    return r;
}
__device__ __forceinline__ float bf16_of(float a) {
    __nv_bfloat16 h = __float2bfloat16(a);
    return __bfloat162float(h);
}

template <bool IS64>
__device__ __forceinline__ void agg_body(const float* __restrict__ x,
                                         const void* __restrict__ edges,
                                         int E, int nN) {
    const int lane = threadIdx.x & 31;
    const int gw = (blockIdx.x * blockDim.x + threadIdx.x) >> 5;
    const int nw = (gridDim.x * blockDim.x) >> 5;
    const float4* __restrict__ xr = (const float4*)x;
    uint4* __restrict__ ga4 = (uint4*)g_a;
    const long long* __restrict__ v64 = (const long long*)edges + E;
    const int* __restrict__ v32 = (const int*)edges + E;

    for (int node = gw; node < NPAD; node += nw) {
        float4 accA = make_float4(0.f, 0.f, 0.f, 0.f);
        float4 accB = make_float4(0.f, 0.f, 0.f, 0.f);
        if (node < nN) {
            const int s = g_row_ptr[node];
            const int e = g_row_ptr[node + 1];
            int j = s;
            for (; j + 4 <= e; j += 4) {
                const int v0 = IS64 ? (int)v64[j + 0] : v32[j + 0];
                const int v1 = IS64 ? (int)v64[j + 1] : v32[j + 1];
                const int v2 = IS64 ? (int)v64[j + 2] : v32[j + 2];
                const int v3 = IS64 ? (int)v64[j + 3] : v32[j + 3];
                const float4 x0 = __ldg(&xr[(size_t)v0 * 32 + lane]);
                const float4 x1 = __ldg(&xr[(size_t)v1 * 32 + lane]);
                const float4 x2 = __ldg(&xr[(size_t)v2 * 32 + lane]);
                const float4 x3 = __ldg(&xr[(size_t)v3 * 32 + lane]);
                accA.x += x0.x; accA.y += x0.y; accA.z += x0.z; accA.w += x0.w;
                accB.x += x1.x; accB.y += x1.y; accB.z += x1.z; accB.w += x1.w;
                accA.x += x2.x; accA.y += x2.y; accA.z += x2.z; accA.w += x2.w;
                accB.x += x3.x; accB.y += x3.y; accB.z += x3.z; accB.w += x3.w;
            }
            for (; j < e; j++) {
                const int v = IS64 ? (int)v64[j] : v32[j];
                const float4 xv = __ldg(&xr[(size_t)v * 32 + lane]);
                accA.x += xv.x; accA.y += xv.y; accA.z += xv.z; accA.w += xv.w;
            }
            accA.x += accB.x; accA.y += accB.y; accA.z += accB.z; accA.w += accB.w;
        }
        uint4 o;
        o.x = pack_hi2(accA.x, accA.y);
        o.y = pack_hi2(accA.x - bf16_of(accA.x), accA.y - bf16_of(accA.y));
        o.z = pack_hi2(accA.z, accA.w);
        o.w = pack_hi2(accA.z - bf16_of(accA.z), accA.w - bf16_of(accA.w));
        ga4[(size_t)node * 32 + lane] = o;
    }
}

__global__ void __launch_bounds__(256) agg_k(const float* __restrict__ x,
                                             const void* __restrict__ edges,
                                             int E, int nN) {
    if (g_ctrl[0] == 0) agg_body<true>(x, edges, E, nN);
    else agg_body<false>(x, edges, E, nN);
}

// ---------------------------------------------------------------------------
// 4) GEMM: persistent blocks, ALL operands in smem during the MMA loop.
//    296 blocks (2/SM) x 128 thr (4 warps). Block tile 64M x 128N; warp tile
//    32M x 64N. B (128x128 hi/lo, 69.6KB) staged ONCE per block; A m-tile
//    (64 rows, 34.8KB) bulk-staged per tile with coalesced uint4 (MLP 16).
//    MMA loop: 24 conflict-free LDS.64 per warp-ks feed 48 HMMA. No LDG in
//    the inner loop -> no L2-latency exposure.
__device__ __forceinline__ void mma_bf16(float* c, const uint32_t* a, const uint32_t* b) {
    asm volatile(
        "mma.sync.aligned.m16n8k16.row.col.f32.bf16.bf16.f32 "
        "{%0,%1,%2,%3}, {%4,%5,%6,%7}, {%8,%9}, {%0,%1,%2,%3};"
        : "+f"(c[0]), "+f"(c[1]), "+f"(c[2]), "+f"(c[3])
        : "r"(a[0]), "r"(a[1]), "r"(a[2]), "r"(a[3]), "r"(b[0]), "r"(b[1]));
}

#define SMA_U2 (64 * AP2)                 // A tile: 64 rows x AP2 uint2
#define SM_BYTES ((SMA_U2 + 128 * AP2) * 8)
#define GEMM_GRID 296

__global__ void __launch_bounds__(128, 2) gemm_k(const float* __restrict__ bias,
                                                 float* __restrict__ out, int nN) {
    extern __shared__ __align__(16) uint2 sm[];
    uint2* __restrict__ smA = sm;
    uint2* __restrict__ smB = sm + SMA_U2;
    const int tid = threadIdx.x;
    const int wid = tid >> 5, lane = tid & 31;
    const int mwarp = wid & 1, nwarp = wid >> 1;
    const int qr = lane >> 2;
    const int qc = (lane & 3) * 2;

    // Stage full B once (128 rows x 34 uint4) = 4352 uint4.
    {
        const uint4* __restrict__ src = (const uint4*)g_wt;
        uint4* __restrict__ dst = (uint4*)smB;
#pragma unroll
        for (int i = 0; i < 34; i++)
            dst[i * 128 + tid] = src[i * 128 + tid];
    }

    for (int tile = blockIdx.x; tile < NTILES; tile += GEMM_GRID) {
        // ---- stage A tile: 64 rows x 32 uint4 (repitch 32 -> 34) ----
        {
            const uint4* __restrict__ src =
                (const uint4*)g_a + (size_t)tile * 64 * 32;
            uint4* __restrict__ dst = (uint4*)smA;
#pragma unroll
            for (int i = 0; i < 16; i++) {
                const int idx = i * 128 + tid;     // 0..2047
                const int r = idx >> 5, c = idx & 31;
                dst[r * (AP2 / 2) + c] = src[idx];
            }
        }
        __syncthreads();

        // ---- MMA from smem only ----
        float acc[2][8][4];
#pragma unroll
        for (int j = 0; j < 2; j++)
#pragma unroll
            for (int nt = 0; nt < 8; nt++)
#pragma unroll
                for (int q = 0; q < 4; q++) acc[j][nt][q] = 0.f;

        const int r0 = mwarp * 32 + qr;
#pragma unroll
        for (int ks = 0; ks < 8; ks++) {
            const int kp0 = ks * 8 + (lane & 3);
            const uint2 a00 = smA[r0 * AP2 + kp0];
            const uint2 a01 = smA[(r0 + 8) * AP2 + kp0];
            const uint2 a02 = smA[r0 * AP2 + kp0 + 4];
            const uint2 a03 = smA[(r0 + 8) * AP2 + kp0 + 4];
            const uint2 a10 = smA[(r0 + 16) * AP2 + kp0];
            const uint2 a11 = smA[(r0 + 24) * AP2 + kp0];
            const uint2 a12 = smA[(r0 + 16) * AP2 + kp0 + 4];
            const uint2 a13 = smA[(r0 + 24) * AP2 + kp0 + 4];
            const uint32_t ahi0[4] = {a00.x, a01.x, a02.x, a03.x};
            const uint32_t alo0[4] = {a00.y, a01.y, a02.y, a03.y};
            const uint32_t ahi1[4] = {a10.x, a11.x, a12.x, a13.x};
            const uint32_t alo1[4] = {a10.y, a11.y, a12.y, a13.y};
#pragma unroll
            for (int nt = 0; nt < 8; nt++) {
                const int brow = nwarp * 64 + nt * 8 + qr;
                const uint2 b0 = smB[brow * AP2 + kp0];
                const uint2 b1 = smB[brow * AP2 + kp0 + 4];
                const uint32_t bhi[2] = {b0.x, b1.x};
                const uint32_t blo[2] = {b0.y, b1.y};
                mma_bf16(acc[0][nt], ahi0, bhi);
                mma_bf16(acc[0][nt], ahi0, blo);
                mma_bf16(acc[0][nt], alo0, bhi);
                mma_bf16(acc[1][nt], ahi1, bhi);
                mma_bf16(acc[1][nt], ahi1, blo);
                mma_bf16(acc[1][nt], alo1, bhi);
            }
        }

        // ---- epilogue ----
#pragma unroll
        for (int j = 0; j < 2; j++) {
            const int m0 = tile * 64 + mwarp * 32 + j * 16 + qr;
#pragma unroll
            for (int nt = 0; nt < 8; nt++) {
                const int n0 = nwarp * 64 + nt * 8 + qc;
                const float2 bv = *(const float2*)&bias[n0];
                if (m0 < nN) {
                    float2 r = make_float2(acc[j][nt][0] + bv.x,
                                           acc[j][nt][1] + bv.y);
                    *(float2*)&out[(size_t)m0 * FDIM + n0] = r;
                }
                if (m0 + 8 < nN) {
                    float2 r = make_float2(acc[j][nt][2] + bv.x,
                                           acc[j][nt][3] + bv.y);
                    *(float2*)&out[(size_t)(m0 + 8) * FDIM + n0] = r;
                }
            }
        }
        __syncthreads();   // protect smA before next tile's restage
    }
}

// ---------------------------------------------------------------------------
extern "C" void kernel_launch(void* const* d_in, const int* in_sizes, int n_in,
                              void* d_out, int out_size) {
    const float* x = (const float*)d_in[0];
    const void* edges = d_in[1];
    const float* W = (const float*)d_in[2];
    const float* bias = (const float*)d_in[3];
    float* out = (float*)d_out;

    const int nN = in_sizes[0] / FDIM;
    int E = in_sizes[1] / 2;
    if (E > MAXE) E = MAXE;

    void* ctrl = nullptr;
    cudaGetSymbolAddress(&ctrl, g_ctrl);
    cudaMemsetAsync(ctrl, 0, sizeof(unsigned int));

    cudaFuncSetAttribute(gemm_k, cudaFuncAttributeMaxDynamicSharedMemorySize, SM_BYTES);

    int npairs = E < 512 ? E : 512;
    detect_k<<<1, 256>>>((const unsigned int*)edges, npairs);
    rowptr_k<<<(nN + 256) / 256, 256>>>(edges, W, E, nN);
    agg_k<<<1184, 256>>>(x, edges, E, nN);
    gemm_k<<<GEMM_GRID, 128, SM_BYTES>>>(bias, out, nN);
}